// round 3
// baseline (speedup 1.0000x reference)
#include <cuda_runtime.h>
#include <math.h>

#define BATCH 4
#define QN    8192
#define DIM   256
#define NQ    (BATCH*QN)        // 32768
#define H0c   128
#define W0c   128
#define H1c   64
#define W1c   64
#define LPTS  16                // L*P
#define NOUT  52                // 4 rd + 32 off + 16 attn
#define NPAD  64                // padded N for proj GEMM
#define EPSV  1e-5f

typedef unsigned long long ull;

// packed f32x2 FMA: acc = a*b + acc (elementwise on 2 packed fp32)
__device__ __forceinline__ void ffma2(ull& acc, ull a, ull b) {
    asm("fma.rn.f32x2 %0, %1, %2, %0;" : "+l"(acc) : "l"(a), "l"(b));
}
__device__ __forceinline__ float2 u2f(ull u) {
    float2 f;
    asm("mov.b64 {%0,%1}, %2;" : "=f"(f.x), "=f"(f.y) : "l"(u));
    return f;
}

// ---------------- scratch (static device arrays; no allocation allowed) ----
__device__ float  g_map0t[BATCH*H0c*W0c*DIM];   // (B,H,W,D)
__device__ float  g_map1t[BATCH*H1c*W1c*DIM];   // (B,H,W,D)
__device__ float  g_inner[(size_t)NQ*DIM];
__device__ float4 g_params[(size_t)NQ*LPTS];    // x, y, attn_w, pad
__device__ float  g_Wk[DIM*NPAD];               // k-major fused weights (cols 52..63 stay 0)
__device__ float  g_bias[NOUT];

// ---------------- 0) weight prep: fuse into k-major layout ------------------
__global__ void wprep_kernel(const float* __restrict__ Wrd,   const float* __restrict__ brd,
                             const float* __restrict__ Woff,  const float* __restrict__ boff,
                             const float* __restrict__ Wattn, const float* __restrict__ battn)
{
    int j = blockIdx.x;          // 0..51
    int d = threadIdx.x;         // 0..255
    float v;
    if (j < 4)        v = Wrd [d*4  + j];
    else if (j < 36)  v = Woff[d*32 + (j-4)];
    else              v = Wattn[d*16 + (j-36)];
    g_Wk[d*NPAD + j] = v;
    if (d == 0) {
        float bv;
        if (j < 4)        bv = brd[j];
        else if (j < 36)  bv = boff[j-4];
        else              bv = battn[j-36];
        g_bias[j] = bv;
    }
}

// ---------------- 1) transpose (B,D,H,W) -> (B,H,W,D) ----------------------
__global__ void transpose_kernel(const float* __restrict__ src, int H, int W, int which)
{
    float* dst = which ? g_map1t : g_map0t;
    __shared__ float tile[32][33];
    int w0 = blockIdx.x * 32;
    int d0 = blockIdx.y * 32;
    int bh = blockIdx.z;
    int b  = bh / H;
    int h  = bh % H;
    int tx = threadIdx.x, ty = threadIdx.y;   // 32 x 8

    const float* s = src + (((size_t)b*DIM + d0)*H + h) * W + w0;
    #pragma unroll
    for (int r = 0; r < 4; r++)
        tile[ty + 8*r][tx] = s[(size_t)(ty + 8*r) * H * W + tx];
    __syncthreads();
    float* dbase = dst + (((size_t)b*H + h)*W + w0) * DIM + d0;
    #pragma unroll
    for (int r = 0; r < 4; r++)
        dbase[(size_t)(ty + 8*r) * DIM + tx] = tile[tx][ty + 8*r];
}

// ---------------- 2) fused projection GEMM + point-param prep ---------------
// GEMM: [128 queries x 256] @ [256 x 64] per block, f32x2 packed FMA.
// Epilogue: results staged in smem, threads 0..127 each finalize one query.
#define PBM 128
#define PBK 32
#define STAGE_PITCH 132
#define PROJ_SMEM (NPAD*STAGE_PITCH*4)   // 33792 B (>= As 16K + Bsd 16K)

__global__ void __launch_bounds__(256) proj_gemm_kernel(const float* __restrict__ q,
                                                        const float* __restrict__ base_ref)
{
    __shared__ __align__(16) char sm[PROJ_SMEM];
    float  (*As)[PBM]  = (float  (*)[PBM]) sm;                  // [PBK][PBM]
    float2 (*Bsd)[NPAD]= (float2 (*)[NPAD])(sm + PBK*PBM*4);    // [PBK][NPAD] dup pairs
    float* stage = (float*)sm;                                   // [NPAD][STAGE_PITCH]

    int tid = threadIdx.x;
    int q0  = blockIdx.x * PBM;
    int tm  = tid & 31;          // query group: queries tm*4 .. tm*4+3
    int tn  = tid >> 5;          // output group: outputs tn*8 .. tn*8+7

    ull acc[2][8];
    #pragma unroll
    for (int p = 0; p < 2; p++)
        #pragma unroll
        for (int j = 0; j < 8; j++) acc[p][j] = 0ull;

    #pragma unroll 1
    for (int kt = 0; kt < DIM/PBK; kt++) {
        int k0 = kt * PBK;
        // load A tile (transposed into [k][m])
        {
            int r = tid >> 1, cb = (tid & 1) * 16;
            #pragma unroll
            for (int i = 0; i < 4; i++) {
                float4 v = *(const float4*)(q + (size_t)(q0 + r)*DIM + k0 + cb + i*4);
                As[cb + i*4 + 0][r] = v.x;
                As[cb + i*4 + 1][r] = v.y;
                As[cb + i*4 + 2][r] = v.z;
                As[cb + i*4 + 3][r] = v.w;
            }
        }
        // load B tile duplicated: Bsd[k][j] = (w, w)
        {
            int kr = tid >> 3, jb = (tid & 7) * 8;
            #pragma unroll
            for (int i = 0; i < 2; i++) {
                float4 w = *(const float4*)(g_Wk + (size_t)(k0 + kr)*NPAD + jb + i*4);
                Bsd[kr][jb + i*4 + 0] = make_float2(w.x, w.x);
                Bsd[kr][jb + i*4 + 1] = make_float2(w.y, w.y);
                Bsd[kr][jb + i*4 + 2] = make_float2(w.z, w.z);
                Bsd[kr][jb + i*4 + 3] = make_float2(w.w, w.w);
            }
        }
        __syncthreads();

        #pragma unroll
        for (int k = 0; k < PBK; k++) {
            longlong2 av = *(const longlong2*)&As[k][tm*4];   // (q0,q1),(q2,q3)
            ull bq[8];
            #pragma unroll
            for (int i = 0; i < 4; i++) {
                longlong2 bv = *((const longlong2*)&Bsd[k][tn*8] + i);
                bq[2*i]   = (ull)bv.x;
                bq[2*i+1] = (ull)bv.y;
            }
            #pragma unroll
            for (int j = 0; j < 8; j++) {
                ffma2(acc[0][j], (ull)av.x, bq[j]);
                ffma2(acc[1][j], (ull)av.y, bq[j]);
            }
        }
        __syncthreads();
    }

    // stage acc -> smem as stage[j][query]
    #pragma unroll
    for (int j = 0; j < 8; j++) {
        #pragma unroll
        for (int p = 0; p < 2; p++) {
            float2 v = u2f(acc[p][j]);
            *(float2*)&stage[(tn*8 + j)*STAGE_PITCH + tm*4 + p*2] = v;
        }
    }
    __syncthreads();

    // epilogue: one thread per query does softmax + coords
    if (tid < PBM) {
        int qi = q0 + tid;
        int b  = qi >> 13;

        float r[NOUT];
        #pragma unroll
        for (int j = 0; j < NOUT; j++)
            r[j] = stage[j*STAGE_PITCH + tid] + g_bias[j];

        // softmax over r[36..51]
        float m = -1e30f;
        #pragma unroll
        for (int j = 0; j < 16; j++) m = fmaxf(m, r[36+j]);
        float sum = 0.f;
        float e[16];
        #pragma unroll
        for (int j = 0; j < 16; j++) { e[j] = expf(r[36+j] - m); sum += e[j]; }
        float inv = 1.f / sum;

        float4* pp = g_params + (size_t)qi * LPTS;
        #pragma unroll
        for (int l = 0; l < 2; l++) {
            float Wf = l ? (float)W1c : (float)W0c;
            float Hf = l ? (float)H1c : (float)H0c;
            float bx = base_ref[b*4 + l*2 + 0];
            float by = base_ref[b*4 + l*2 + 1];
            bx = fminf(fmaxf(bx, EPSV), 1.f - EPSV);
            by = fminf(fmaxf(by, EPSV), 1.f - EPSV);
            float lbx = logf(bx / (1.f - bx));
            float lby = logf(by / (1.f - by));
            float refx = 1.f / (1.f + expf(-(lbx + r[l*2 + 0])));
            float refy = 1.f / (1.f + expf(-(lby + r[l*2 + 1])));

            #pragma unroll
            for (int p = 0; p < 8; p++) {
                int pt = l*8 + p;
                float ox = r[4 + pt*2 + 0];
                float oy = r[4 + pt*2 + 1];
                float lx = refx + ox / Wf;
                float ly = refy + oy / Hf;
                if (l == 1) ly = ly - floorf(ly);      // jnp.remainder(., 1.0)
                float x = lx * Wf - 0.5f;
                float y = ly * Hf - 0.5f;
                x = fminf(fmaxf(x, 0.f), Wf - 1.f);
                y = fminf(fmaxf(y, 0.f), Hf - 1.f);
                pp[pt] = make_float4(x, y, e[pt]*inv, 0.f);
            }
        }
    }
}

// ---------------- 3) sampling: 64-thread group per query, float4 channels --
__global__ void sample_kernel()
{
    int g  = threadIdx.x >> 6;           // 4 queries per 256-thread block
    int t  = threadIdx.x & 63;           // channel group: channels 4t..4t+3
    int qi = blockIdx.x * 4 + g;
    int b  = qi >> 13;

    const float4* pp = g_params + (size_t)qi * LPTS;
    const float* m0 = g_map0t + (size_t)b * (H0c*W0c*DIM);
    const float* m1 = g_map1t + (size_t)b * (H1c*W1c*DIM);

    float4 acc = make_float4(0.f, 0.f, 0.f, 0.f);

    #pragma unroll
    for (int p = 0; p < 16; p++) {
        float4 par = __ldg(&pp[p]);
        const float* mp = (p < 8) ? m0 : m1;
        const int Wl = (p < 8) ? W0c : W1c;
        const int Hl = (p < 8) ? H0c : H1c;

        float x = par.x, y = par.y, wt = par.z;
        int x0 = (int)x, y0 = (int)y;
        float wx = x - (float)x0;
        float wy = y - (float)y0;
        int x1 = min(x0 + 1, Wl - 1);
        int y1 = min(y0 + 1, Hl - 1);

        float4 v00 = __ldg((const float4*)(mp + (size_t)(y0*Wl + x0) * DIM) + t);
        float4 v01 = __ldg((const float4*)(mp + (size_t)(y0*Wl + x1) * DIM) + t);
        float4 v10 = __ldg((const float4*)(mp + (size_t)(y1*Wl + x0) * DIM) + t);
        float4 v11 = __ldg((const float4*)(mp + (size_t)(y1*Wl + x1) * DIM) + t);

        float w00 = (1.f - wx) * (1.f - wy) * wt;
        float w01 = wx * (1.f - wy) * wt;
        float w10 = (1.f - wx) * wy * wt;
        float w11 = wx * wy * wt;

        acc.x = fmaf(w00, v00.x, fmaf(w01, v01.x, fmaf(w10, v10.x, fmaf(w11, v11.x, acc.x))));
        acc.y = fmaf(w00, v00.y, fmaf(w01, v01.y, fmaf(w10, v10.y, fmaf(w11, v11.y, acc.y))));
        acc.z = fmaf(w00, v00.z, fmaf(w01, v01.z, fmaf(w10, v10.z, fmaf(w11, v11.z, acc.z))));
        acc.w = fmaf(w00, v00.w, fmaf(w01, v01.w, fmaf(w10, v10.w, fmaf(w11, v11.w, acc.w))));
    }

    ((float4*)(g_inner + (size_t)qi * DIM))[t] = acc;
}

// ---------------- 4) SGEMM with packed f32x2: out = g_inner @ Wout + bout ---
__global__ void __launch_bounds__(256) gemm_kernel(const float* __restrict__ Wout,
                                                   const float* __restrict__ bout,
                                                   float* __restrict__ out)
{
    const int BM = 128, BN = 128, BK = 8;
    __shared__ __align__(16) float  As[BK][BM];
    __shared__ __align__(16) float2 Bsd[BK][BN];    // duplicated pairs

    int bx = blockIdx.x;   // 0..1
    int by = blockIdx.y;   // 0..255
    int tid = threadIdx.x;
    int tx = tid & 15;     // col group
    int ty = tid >> 4;     // row group

    const float* A  = g_inner + (size_t)by * BM * 256;
    const float* Bp = Wout + bx * BN;
    float* C = out + (size_t)by * BM * 256 + bx * BN;

    int arow = tid >> 1,  acol = (tid & 1) * 4;
    int brow = tid >> 5,  bcol = (tid & 31) * 4;

    ull acc[4][8];
    #pragma unroll
    for (int i = 0; i < 4; i++)
        #pragma unroll
        for (int j = 0; j < 8; j++) acc[i][j] = 0ull;

    #pragma unroll 1
    for (int k0 = 0; k0 < 256; k0 += BK) {
        float4 a4 = *(const float4*)(A + (size_t)arow * 256 + k0 + acol);
        As[acol + 0][arow] = a4.x;
        As[acol + 1][arow] = a4.y;
        As[acol + 2][arow] = a4.z;
        As[acol + 3][arow] = a4.w;
        float4 b4 = *(const float4*)(Bp + (size_t)(k0 + brow) * 256 + bcol);
        Bsd[brow][bcol + 0] = make_float2(b4.x, b4.x);
        Bsd[brow][bcol + 1] = make_float2(b4.y, b4.y);
        Bsd[brow][bcol + 2] = make_float2(b4.z, b4.z);
        Bsd[brow][bcol + 3] = make_float2(b4.w, b4.w);
        __syncthreads();

        #pragma unroll
        for (int k = 0; k < BK; k++) {
            longlong2 ra0 = *(const longlong2*)&As[k][ty*8];
            longlong2 ra1 = *(const longlong2*)&As[k][ty*8 + 4];
            ull a[4] = {(ull)ra0.x, (ull)ra0.y, (ull)ra1.x, (ull)ra1.y};
            ull bq[8];
            #pragma unroll
            for (int i = 0; i < 4; i++) {
                longlong2 bv = *((const longlong2*)&Bsd[k][tx*8] + i);
                bq[2*i]   = (ull)bv.x;
                bq[2*i+1] = (ull)bv.y;
            }
            #pragma unroll
            for (int ip = 0; ip < 4; ip++)
                #pragma unroll
                for (int j = 0; j < 8; j++)
                    ffma2(acc[ip][j], a[ip], bq[j]);
        }
        __syncthreads();
    }

    #pragma unroll
    for (int i = 0; i < 8; i++) {
        int ip = i >> 1, hi = i & 1;
        #pragma unroll
        for (int j = 0; j < 8; j += 4) {
            int col = bx * BN + tx * 8 + j;
            float2 f0 = u2f(acc[ip][j + 0]);
            float2 f1 = u2f(acc[ip][j + 1]);
            float2 f2 = u2f(acc[ip][j + 2]);
            float2 f3 = u2f(acc[ip][j + 3]);
            float4 r;
            r.x = (hi ? f0.y : f0.x) + __ldg(&bout[col + 0]);
            r.y = (hi ? f1.y : f1.x) + __ldg(&bout[col + 1]);
            r.z = (hi ? f2.y : f2.x) + __ldg(&bout[col + 2]);
            r.w = (hi ? f3.y : f3.x) + __ldg(&bout[col + 3]);
            *(float4*)(C + (size_t)(ty * 8 + i) * 256 + tx * 8 + j) = r;
        }
    }
}

// ---------------- launch -----------------------------------------------------
extern "C" void kernel_launch(void* const* d_in, const int* in_sizes, int n_in,
                              void* d_out, int out_size)
{
    const float* q        = (const float*)d_in[0];
    const float* map0     = (const float*)d_in[1];
    const float* map1     = (const float*)d_in[2];
    const float* base_ref = (const float*)d_in[3];
    const float* Wrd      = (const float*)d_in[4];
    const float* brd      = (const float*)d_in[5];
    const float* Woff     = (const float*)d_in[6];
    const float* boff     = (const float*)d_in[7];
    const float* Wattn    = (const float*)d_in[8];
    const float* battn    = (const float*)d_in[9];
    const float* Wout     = (const float*)d_in[10];
    const float* bout     = (const float*)d_in[11];
    float* out = (float*)d_out;

    wprep_kernel<<<NOUT, 256>>>(Wrd, brd, Woff, boff, Wattn, battn);

    transpose_kernel<<<dim3(W0c/32, DIM/32, BATCH*H0c), dim3(32, 8)>>>(map0, H0c, W0c, 0);
    transpose_kernel<<<dim3(W1c/32, DIM/32, BATCH*H1c), dim3(32, 8)>>>(map1, H1c, W1c, 1);

    proj_gemm_kernel<<<NQ/PBM, 256>>>(q, base_ref);

    sample_kernel<<<NQ/4, 256>>>();

    gemm_kernel<<<dim3(2, NQ/128), 256>>>(Wout, bout, out);
}

// round 4
// speedup vs baseline: 1.6379x; 1.6379x over previous
#include <cuda_runtime.h>
#include <math.h>

#define BATCH 4
#define QN    8192
#define DIM   256
#define NQ    (BATCH*QN)        // 32768
#define H0c   128
#define W0c   128
#define H1c   64
#define W1c   64
#define LPTS  16                // L*P
#define NOUT  52                // 4 rd + 32 off + 16 attn
#define NPAD  64                // padded N for proj GEMM
#define EPSV  1e-5f

typedef unsigned long long ull;

// packed f32x2 FMA: acc = a*b + acc (elementwise on 2 packed fp32)
__device__ __forceinline__ void ffma2(ull& acc, ull a, ull b) {
    asm("fma.rn.f32x2 %0, %1, %2, %0;" : "+l"(acc) : "l"(a), "l"(b));
}
__device__ __forceinline__ float2 u2f(ull u) {
    float2 f;
    asm("mov.b64 {%0,%1}, %2;" : "=f"(f.x), "=f"(f.y) : "l"(u));
    return f;
}

// ---------------- scratch (static device arrays; no allocation allowed) ----
__device__ float  g_map0t[BATCH*H0c*W0c*DIM];   // (B,H,W,D)
__device__ float  g_map1t[BATCH*H1c*W1c*DIM];   // (B,H,W,D)
__device__ float  g_inner[(size_t)NQ*DIM];
__device__ float4 g_params[(size_t)NQ*LPTS];    // x, y, attn_w, pad
__device__ float  g_Wk[DIM*NPAD];               // k-major fused weights (cols 52..63 stay 0)
__device__ float  g_bias[NOUT];

// ---------------- 0) weight prep: fuse into k-major layout ------------------
__global__ void wprep_kernel(const float* __restrict__ Wrd,   const float* __restrict__ brd,
                             const float* __restrict__ Woff,  const float* __restrict__ boff,
                             const float* __restrict__ Wattn, const float* __restrict__ battn)
{
    int j = blockIdx.x;          // 0..51
    int d = threadIdx.x;         // 0..255
    float v;
    if (j < 4)        v = Wrd [d*4  + j];
    else if (j < 36)  v = Woff[d*32 + (j-4)];
    else              v = Wattn[d*16 + (j-36)];
    g_Wk[d*NPAD + j] = v;
    if (d == 0) {
        float bv;
        if (j < 4)        bv = brd[j];
        else if (j < 36)  bv = boff[j-4];
        else              bv = battn[j-36];
        g_bias[j] = bv;
    }
}

// ---------------- 1) transpose (B,D,H,W) -> (B,H,W,D) ----------------------
__global__ void transpose_kernel(const float* __restrict__ src, int H, int W, int which)
{
    float* dst = which ? g_map1t : g_map0t;
    __shared__ float tile[32][33];
    int w0 = blockIdx.x * 32;
    int d0 = blockIdx.y * 32;
    int bh = blockIdx.z;
    int b  = bh / H;
    int h  = bh % H;
    int tx = threadIdx.x, ty = threadIdx.y;   // 32 x 8

    const float* s = src + (((size_t)b*DIM + d0)*H + h) * W + w0;
    #pragma unroll
    for (int r = 0; r < 4; r++)
        tile[ty + 8*r][tx] = s[(size_t)(ty + 8*r) * H * W + tx];
    __syncthreads();
    float* dbase = dst + (((size_t)b*H + h)*W + w0) * DIM + d0;
    #pragma unroll
    for (int r = 0; r < 4; r++)
        dbase[(size_t)(ty + 8*r) * DIM + tx] = tile[tx][ty + 8*r];
}

// ---------------- 2) fused projection GEMM + point-param prep ---------------
// GEMM: [128 queries x 256] @ [256 x 64] per block, f32x2 packed FMA.
// Epilogue: results staged in smem, threads 0..127 each finalize one query.
#define PBM 128
#define PBK 32
#define STAGE_PITCH 132
#define PROJ_SMEM (NPAD*STAGE_PITCH*4)   // 33792 B (>= As 16K + Bsd 16K)

__global__ void __launch_bounds__(256) proj_gemm_kernel(const float* __restrict__ q,
                                                        const float* __restrict__ base_ref)
{
    __shared__ __align__(16) char sm[PROJ_SMEM];
    float  (*As)[PBM]  = (float  (*)[PBM]) sm;                  // [PBK][PBM]
    float2 (*Bsd)[NPAD]= (float2 (*)[NPAD])(sm + PBK*PBM*4);    // [PBK][NPAD] dup pairs
    float* stage = (float*)sm;                                   // [NPAD][STAGE_PITCH]

    int tid = threadIdx.x;
    int q0  = blockIdx.x * PBM;
    int tm  = tid & 31;          // query group: queries tm*4 .. tm*4+3
    int tn  = tid >> 5;          // output group: outputs tn*8 .. tn*8+7

    ull acc[2][8];
    #pragma unroll
    for (int p = 0; p < 2; p++)
        #pragma unroll
        for (int j = 0; j < 8; j++) acc[p][j] = 0ull;

    #pragma unroll 1
    for (int kt = 0; kt < DIM/PBK; kt++) {
        int k0 = kt * PBK;
        // load A tile (transposed into [k][m])
        {
            int r = tid >> 1, cb = (tid & 1) * 16;
            #pragma unroll
            for (int i = 0; i < 4; i++) {
                float4 v = *(const float4*)(q + (size_t)(q0 + r)*DIM + k0 + cb + i*4);
                As[cb + i*4 + 0][r] = v.x;
                As[cb + i*4 + 1][r] = v.y;
                As[cb + i*4 + 2][r] = v.z;
                As[cb + i*4 + 3][r] = v.w;
            }
        }
        // load B tile duplicated: Bsd[k][j] = (w, w)
        {
            int kr = tid >> 3, jb = (tid & 7) * 8;
            #pragma unroll
            for (int i = 0; i < 2; i++) {
                float4 w = *(const float4*)(g_Wk + (size_t)(k0 + kr)*NPAD + jb + i*4);
                Bsd[kr][jb + i*4 + 0] = make_float2(w.x, w.x);
                Bsd[kr][jb + i*4 + 1] = make_float2(w.y, w.y);
                Bsd[kr][jb + i*4 + 2] = make_float2(w.z, w.z);
                Bsd[kr][jb + i*4 + 3] = make_float2(w.w, w.w);
            }
        }
        __syncthreads();

        #pragma unroll
        for (int k = 0; k < PBK; k++) {
            longlong2 av = *(const longlong2*)&As[k][tm*4];   // (q0,q1),(q2,q3)
            ull bq[8];
            #pragma unroll
            for (int i = 0; i < 4; i++) {
                longlong2 bv = *((const longlong2*)&Bsd[k][tn*8] + i);
                bq[2*i]   = (ull)bv.x;
                bq[2*i+1] = (ull)bv.y;
            }
            #pragma unroll
            for (int j = 0; j < 8; j++) {
                ffma2(acc[0][j], (ull)av.x, bq[j]);
                ffma2(acc[1][j], (ull)av.y, bq[j]);
            }
        }
        __syncthreads();
    }

    // stage acc -> smem as stage[j][query]
    #pragma unroll
    for (int j = 0; j < 8; j++) {
        #pragma unroll
        for (int p = 0; p < 2; p++) {
            float2 v = u2f(acc[p][j]);
            *(float2*)&stage[(tn*8 + j)*STAGE_PITCH + tm*4 + p*2] = v;
        }
    }
    __syncthreads();

    // epilogue: one thread per query does softmax + coords
    if (tid < PBM) {
        int qi = q0 + tid;
        int b  = qi >> 13;

        float r[NOUT];
        #pragma unroll
        for (int j = 0; j < NOUT; j++)
            r[j] = stage[j*STAGE_PITCH + tid] + g_bias[j];

        // softmax over r[36..51]
        float m = -1e30f;
        #pragma unroll
        for (int j = 0; j < 16; j++) m = fmaxf(m, r[36+j]);
        float sum = 0.f;
        float e[16];
        #pragma unroll
        for (int j = 0; j < 16; j++) { e[j] = expf(r[36+j] - m); sum += e[j]; }
        float inv = 1.f / sum;

        float4* pp = g_params + (size_t)qi * LPTS;
        #pragma unroll
        for (int l = 0; l < 2; l++) {
            float Wf = l ? (float)W1c : (float)W0c;
            float Hf = l ? (float)H1c : (float)H0c;
            float bx = base_ref[b*4 + l*2 + 0];
            float by = base_ref[b*4 + l*2 + 1];
            bx = fminf(fmaxf(bx, EPSV), 1.f - EPSV);
            by = fminf(fmaxf(by, EPSV), 1.f - EPSV);
            float lbx = logf(bx / (1.f - bx));
            float lby = logf(by / (1.f - by));
            float refx = 1.f / (1.f + expf(-(lbx + r[l*2 + 0])));
            float refy = 1.f / (1.f + expf(-(lby + r[l*2 + 1])));

            #pragma unroll
            for (int p = 0; p < 8; p++) {
                int pt = l*8 + p;
                float ox = r[4 + pt*2 + 0];
                float oy = r[4 + pt*2 + 1];
                float lx = refx + ox / Wf;
                float ly = refy + oy / Hf;
                if (l == 1) ly = ly - floorf(ly);      // jnp.remainder(., 1.0)
                float x = lx * Wf - 0.5f;
                float y = ly * Hf - 0.5f;
                x = fminf(fmaxf(x, 0.f), Wf - 1.f);
                y = fminf(fmaxf(y, 0.f), Hf - 1.f);
                pp[pt] = make_float4(x, y, e[pt]*inv, 0.f);
            }
        }
    }
}

// ---------------- 3) sampling: 64-thread group per query, 8 queries/block --
__global__ void __launch_bounds__(512) sample_kernel()
{
    int g  = threadIdx.x >> 6;           // 8 queries per 512-thread block
    int t  = threadIdx.x & 63;           // channel group: channels 4t..4t+3
    int qi = blockIdx.x * 8 + g;
    int b  = qi >> 13;

    const float4* pp = g_params + (size_t)qi * LPTS;
    const float* m0 = g_map0t + (size_t)b * (H0c*W0c*DIM);
    const float* m1 = g_map1t + (size_t)b * (H1c*W1c*DIM);

    float4 acc = make_float4(0.f, 0.f, 0.f, 0.f);

    #pragma unroll
    for (int p = 0; p < 16; p++) {
        float4 par = __ldg(&pp[p]);
        const float* mp = (p < 8) ? m0 : m1;
        const int Wl = (p < 8) ? W0c : W1c;
        const int Hl = (p < 8) ? H0c : H1c;

        float x = par.x, y = par.y, wt = par.z;
        int x0 = (int)x, y0 = (int)y;
        float wx = x - (float)x0;
        float wy = y - (float)y0;
        int x1 = min(x0 + 1, Wl - 1);
        int y1 = min(y0 + 1, Hl - 1);

        float4 v00 = __ldg((const float4*)(mp + (size_t)(y0*Wl + x0) * DIM) + t);
        float4 v01 = __ldg((const float4*)(mp + (size_t)(y0*Wl + x1) * DIM) + t);
        float4 v10 = __ldg((const float4*)(mp + (size_t)(y1*Wl + x0) * DIM) + t);
        float4 v11 = __ldg((const float4*)(mp + (size_t)(y1*Wl + x1) * DIM) + t);

        float w00 = (1.f - wx) * (1.f - wy) * wt;
        float w01 = wx * (1.f - wy) * wt;
        float w10 = (1.f - wx) * wy * wt;
        float w11 = wx * wy * wt;

        acc.x = fmaf(w00, v00.x, fmaf(w01, v01.x, fmaf(w10, v10.x, fmaf(w11, v11.x, acc.x))));
        acc.y = fmaf(w00, v00.y, fmaf(w01, v01.y, fmaf(w10, v10.y, fmaf(w11, v11.y, acc.y))));
        acc.z = fmaf(w00, v00.z, fmaf(w01, v01.z, fmaf(w10, v10.z, fmaf(w11, v11.z, acc.z))));
        acc.w = fmaf(w00, v00.w, fmaf(w01, v01.w, fmaf(w10, v10.w, fmaf(w11, v11.w, acc.w))));
    }

    ((float4*)(g_inner + (size_t)qi * DIM))[t] = acc;
}

// ---------------- 4) SGEMM (scalar FFMA, known-good): out = g_inner @ Wout + bout
// M=32768, N=256, K=256. BM=BN=128, BK=8, 8x8 per thread, 256 threads.
__global__ void gemm_kernel(const float* __restrict__ Wout,
                            const float* __restrict__ bout,
                            float* __restrict__ out)
{
    const int BM = 128, BN = 128, BK = 8;
    __shared__ __align__(16) float As[BK][BM];
    __shared__ __align__(16) float Bs[BK][BN];

    int bx = blockIdx.x;   // 0..1
    int by = blockIdx.y;   // 0..255
    int tid = threadIdx.x; // 256
    int tx = tid & 15;     // col group
    int ty = tid >> 4;     // row group

    const float* A = g_inner + (size_t)by * BM * 256;
    const float* Bp = Wout + bx * BN;
    float* C = out + (size_t)by * BM * 256 + bx * BN;

    int arow = tid >> 1,  acol = (tid & 1) * 4;   // A tile load: 128x8
    int brow = tid >> 5,  bcol = (tid & 31) * 4;  // B tile load: 8x128

    float acc[8][8];
    #pragma unroll
    for (int i = 0; i < 8; i++)
        #pragma unroll
        for (int j = 0; j < 8; j++) acc[i][j] = 0.f;

    for (int k0 = 0; k0 < 256; k0 += BK) {
        float4 a4 = *(const float4*)(A + (size_t)arow * 256 + k0 + acol);
        As[acol + 0][arow] = a4.x;
        As[acol + 1][arow] = a4.y;
        As[acol + 2][arow] = a4.z;
        As[acol + 3][arow] = a4.w;
        float4 b4 = *(const float4*)(Bp + (size_t)(k0 + brow) * 256 + bcol);
        *(float4*)&Bs[brow][bcol] = b4;
        __syncthreads();

        #pragma unroll
        for (int k = 0; k < BK; k++) {
            float4 ra0 = *(const float4*)&As[k][ty*8];
            float4 ra1 = *(const float4*)&As[k][ty*8 + 4];
            float4 rb0 = *(const float4*)&Bs[k][tx*8];
            float4 rb1 = *(const float4*)&Bs[k][tx*8 + 4];
            float ra[8] = {ra0.x, ra0.y, ra0.z, ra0.w, ra1.x, ra1.y, ra1.z, ra1.w};
            float rb[8] = {rb0.x, rb0.y, rb0.z, rb0.w, rb1.x, rb1.y, rb1.z, rb1.w};
            #pragma unroll
            for (int i = 0; i < 8; i++)
                #pragma unroll
                for (int j = 0; j < 8; j++)
                    acc[i][j] = fmaf(ra[i], rb[j], acc[i][j]);
        }
        __syncthreads();
    }

    #pragma unroll
    for (int i = 0; i < 8; i++) {
        #pragma unroll
        for (int j = 0; j < 8; j += 4) {
            int col = bx * BN + tx * 8 + j;
            float4 r;
            r.x = acc[i][j + 0] + __ldg(&bout[col + 0]);
            r.y = acc[i][j + 1] + __ldg(&bout[col + 1]);
            r.z = acc[i][j + 2] + __ldg(&bout[col + 2]);
            r.w = acc[i][j + 3] + __ldg(&bout[col + 3]);
            *(float4*)(C + (size_t)(ty * 8 + i) * 256 + tx * 8 + j) = r;
        }
    }
}

// ---------------- launch -----------------------------------------------------
extern "C" void kernel_launch(void* const* d_in, const int* in_sizes, int n_in,
                              void* d_out, int out_size)
{
    const float* q        = (const float*)d_in[0];
    const float* map0     = (const float*)d_in[1];
    const float* map1     = (const float*)d_in[2];
    const float* base_ref = (const float*)d_in[3];
    const float* Wrd      = (const float*)d_in[4];
    const float* brd      = (const float*)d_in[5];
    const float* Woff     = (const float*)d_in[6];
    const float* boff     = (const float*)d_in[7];
    const float* Wattn    = (const float*)d_in[8];
    const float* battn    = (const float*)d_in[9];
    const float* Wout     = (const float*)d_in[10];
    const float* bout     = (const float*)d_in[11];
    float* out = (float*)d_out;

    wprep_kernel<<<NOUT, 256>>>(Wrd, brd, Woff, boff, Wattn, battn);

    transpose_kernel<<<dim3(W0c/32, DIM/32, BATCH*H0c), dim3(32, 8)>>>(map0, H0c, W0c, 0);
    transpose_kernel<<<dim3(W1c/32, DIM/32, BATCH*H1c), dim3(32, 8)>>>(map1, H1c, W1c, 1);

    proj_gemm_kernel<<<NQ/PBM, 256>>>(q, base_ref);

    sample_kernel<<<NQ/8, 512>>>();

    gemm_kernel<<<dim3(2, NQ/128), 256>>>(Wout, bout, out);
}

// round 5
// speedup vs baseline: 1.7338x; 1.0586x over previous
#include <cuda_runtime.h>
#include <cuda_fp16.h>
#include <math.h>

#define BATCH 4
#define QN    8192
#define DIM   256
#define NQ    (BATCH*QN)        // 32768
#define H0c   128
#define W0c   128
#define H1c   64
#define W1c   64
#define LPTS  16                // L*P
#define NOUT  52                // 4 rd + 32 off + 16 attn
#define NPAD  64                // padded N for proj GEMM
#define EPSV  1e-5f

typedef unsigned long long ull;

// packed f32x2 FMA: acc = a*b + acc (elementwise on 2 packed fp32)
__device__ __forceinline__ void ffma2(ull& acc, ull a, ull b) {
    asm("fma.rn.f32x2 %0, %1, %2, %0;" : "+l"(acc) : "l"(a), "l"(b));
}
__device__ __forceinline__ float2 u2f(ull u) {
    float2 f;
    asm("mov.b64 {%0,%1}, %2;" : "=f"(f.x), "=f"(f.y) : "l"(u));
    return f;
}

// ---------------- scratch (static device arrays; no allocation allowed) ----
__device__ __half g_map0t[BATCH*H0c*W0c*DIM];   // (B,H,W,D) fp16
__device__ __half g_map1t[BATCH*H1c*W1c*DIM];   // (B,H,W,D) fp16
__device__ float  g_inner[(size_t)NQ*DIM];
__device__ float4 g_params[(size_t)NQ*LPTS];    // x, y, attn_w, pad
__device__ float  g_Wk[DIM*NPAD];               // k-major fused weights (cols 52..63 stay 0)
__device__ float  g_bias[NOUT];

// ---------------- 0) weight prep: fuse into k-major layout ------------------
__global__ void wprep_kernel(const float* __restrict__ Wrd,   const float* __restrict__ brd,
                             const float* __restrict__ Woff,  const float* __restrict__ boff,
                             const float* __restrict__ Wattn, const float* __restrict__ battn)
{
    int j = blockIdx.x;          // 0..51
    int d = threadIdx.x;         // 0..255
    float v;
    if (j < 4)        v = Wrd [d*4  + j];
    else if (j < 36)  v = Woff[d*32 + (j-4)];
    else              v = Wattn[d*16 + (j-36)];
    g_Wk[d*NPAD + j] = v;
    if (d == 0) {
        float bv;
        if (j < 4)        bv = brd[j];
        else if (j < 36)  bv = boff[j-4];
        else              bv = battn[j-36];
        g_bias[j] = bv;
    }
}

// ---------------- 1) transpose (B,D,H,W) fp32 -> (B,H,W,D) fp16 -------------
__global__ void transpose_kernel(const float* __restrict__ src, int H, int W, int which)
{
    __half* dst = which ? g_map1t : g_map0t;
    __shared__ float tile[32][33];
    int w0 = blockIdx.x * 32;
    int d0 = blockIdx.y * 32;
    int bh = blockIdx.z;
    int b  = bh / H;
    int h  = bh % H;
    int tx = threadIdx.x, ty = threadIdx.y;   // 32 x 8

    const float* s = src + (((size_t)b*DIM + d0)*H + h) * W + w0;
    #pragma unroll
    for (int r = 0; r < 4; r++)
        tile[ty + 8*r][tx] = s[(size_t)(ty + 8*r) * H * W + tx];
    __syncthreads();
    __half* dbase = dst + (((size_t)b*H + h)*W + w0) * DIM + d0;
    #pragma unroll
    for (int r = 0; r < 4; r++)
        dbase[(size_t)(ty + 8*r) * DIM + tx] = __float2half(tile[tx][ty + 8*r]);
}

// ---------------- 2) fused projection GEMM + point-param prep ---------------
// GEMM: [64 queries x 256] @ [256 x 64] per block (grid=512 for occupancy).
#define PBM 64
#define PBK 32
#define STAGE_PITCH 68
#define PROJ_SMEM (PBK*PBM*4 + PBK*NPAD*8)   // 8192 + 16384 = 24576 B

__global__ void __launch_bounds__(256) proj_gemm_kernel(const float* __restrict__ q,
                                                        const float* __restrict__ base_ref)
{
    __shared__ __align__(16) char sm[PROJ_SMEM];
    float  (*As)[PBM]   = (float  (*)[PBM]) sm;                 // [PBK][PBM]
    float2 (*Bsd)[NPAD] = (float2 (*)[NPAD])(sm + PBK*PBM*4);   // [PBK][NPAD] dup pairs
    float* stage = (float*)sm;                                   // [NPAD][STAGE_PITCH] (17408 B)

    int tid = threadIdx.x;
    int q0  = blockIdx.x * PBM;
    int tm  = tid & 15;          // query group: queries tm*4 .. tm*4+3
    int tn  = tid >> 4;          // output group: outputs tn*4 .. tn*4+3

    ull acc[2][4];
    #pragma unroll
    for (int p = 0; p < 2; p++)
        #pragma unroll
        for (int j = 0; j < 4; j++) acc[p][j] = 0ull;

    #pragma unroll 1
    for (int kt = 0; kt < DIM/PBK; kt++) {
        int k0 = kt * PBK;
        // A tile: 64 rows x 32 k, transposed into As[k][m]
        {
            int r = tid >> 2, cb = (tid & 3) * 8;
            float4 v0 = *(const float4*)(q + (size_t)(q0 + r)*DIM + k0 + cb);
            float4 v1 = *(const float4*)(q + (size_t)(q0 + r)*DIM + k0 + cb + 4);
            As[cb + 0][r] = v0.x;  As[cb + 1][r] = v0.y;
            As[cb + 2][r] = v0.z;  As[cb + 3][r] = v0.w;
            As[cb + 4][r] = v1.x;  As[cb + 5][r] = v1.y;
            As[cb + 6][r] = v1.z;  As[cb + 7][r] = v1.w;
        }
        // B tile duplicated: Bsd[k][j] = (w, w)
        {
            int kr = tid >> 3, jb = (tid & 7) * 8;
            float4 w0 = *(const float4*)(g_Wk + (size_t)(k0 + kr)*NPAD + jb);
            float4 w1 = *(const float4*)(g_Wk + (size_t)(k0 + kr)*NPAD + jb + 4);
            Bsd[kr][jb + 0] = make_float2(w0.x, w0.x);
            Bsd[kr][jb + 1] = make_float2(w0.y, w0.y);
            Bsd[kr][jb + 2] = make_float2(w0.z, w0.z);
            Bsd[kr][jb + 3] = make_float2(w0.w, w0.w);
            Bsd[kr][jb + 4] = make_float2(w1.x, w1.x);
            Bsd[kr][jb + 5] = make_float2(w1.y, w1.y);
            Bsd[kr][jb + 6] = make_float2(w1.z, w1.z);
            Bsd[kr][jb + 7] = make_float2(w1.w, w1.w);
        }
        __syncthreads();

        #pragma unroll
        for (int k = 0; k < PBK; k++) {
            longlong2 av = *(const longlong2*)&As[k][tm*4];   // (q0,q1),(q2,q3)
            longlong2 b0 = *((const longlong2*)&Bsd[k][tn*4]);
            longlong2 b1 = *((const longlong2*)&Bsd[k][tn*4] + 1);
            ull bq[4] = {(ull)b0.x, (ull)b0.y, (ull)b1.x, (ull)b1.y};
            #pragma unroll
            for (int j = 0; j < 4; j++) {
                ffma2(acc[0][j], (ull)av.x, bq[j]);
                ffma2(acc[1][j], (ull)av.y, bq[j]);
            }
        }
        __syncthreads();
    }

    // stage acc -> smem as stage[j][query]
    #pragma unroll
    for (int j = 0; j < 4; j++) {
        #pragma unroll
        for (int p = 0; p < 2; p++) {
            float2 v = u2f(acc[p][j]);
            *(float2*)&stage[(tn*4 + j)*STAGE_PITCH + tm*4 + p*2] = v;
        }
    }
    __syncthreads();

    // epilogue: one thread per query does softmax + coords
    if (tid < PBM) {
        int qi = q0 + tid;
        int b  = qi >> 13;

        float r[NOUT];
        #pragma unroll
        for (int j = 0; j < NOUT; j++)
            r[j] = stage[j*STAGE_PITCH + tid] + g_bias[j];

        // softmax over r[36..51]
        float m = -1e30f;
        #pragma unroll
        for (int j = 0; j < 16; j++) m = fmaxf(m, r[36+j]);
        float sum = 0.f;
        float e[16];
        #pragma unroll
        for (int j = 0; j < 16; j++) { e[j] = expf(r[36+j] - m); sum += e[j]; }
        float inv = 1.f / sum;

        float4* pp = g_params + (size_t)qi * LPTS;
        #pragma unroll
        for (int l = 0; l < 2; l++) {
            float Wf = l ? (float)W1c : (float)W0c;
            float Hf = l ? (float)H1c : (float)H0c;
            float bx = base_ref[b*4 + l*2 + 0];
            float by = base_ref[b*4 + l*2 + 1];
            bx = fminf(fmaxf(bx, EPSV), 1.f - EPSV);
            by = fminf(fmaxf(by, EPSV), 1.f - EPSV);
            float lbx = logf(bx / (1.f - bx));
            float lby = logf(by / (1.f - by));
            float refx = 1.f / (1.f + expf(-(lbx + r[l*2 + 0])));
            float refy = 1.f / (1.f + expf(-(lby + r[l*2 + 1])));

            #pragma unroll
            for (int p = 0; p < 8; p++) {
                int pt = l*8 + p;
                float ox = r[4 + pt*2 + 0];
                float oy = r[4 + pt*2 + 1];
                float lx = refx + ox / Wf;
                float ly = refy + oy / Hf;
                if (l == 1) ly = ly - floorf(ly);      // jnp.remainder(., 1.0)
                float x = lx * Wf - 0.5f;
                float y = ly * Hf - 0.5f;
                x = fminf(fmaxf(x, 0.f), Wf - 1.f);
                y = fminf(fmaxf(y, 0.f), Hf - 1.f);
                pp[pt] = make_float4(x, y, e[pt]*inv, 0.f);
            }
        }
    }
}

// ---------------- 3) sampling: fp16 maps, 1 warp per query ------------------
__global__ void __launch_bounds__(512) sample_kernel()
{
    int g  = threadIdx.x >> 5;           // 16 queries per 512-thread block
    int t  = threadIdx.x & 31;           // channel group: channels 8t..8t+7
    int qi = blockIdx.x * 16 + g;
    int b  = qi >> 13;

    const float4* pp = g_params + (size_t)qi * LPTS;
    const __half* m0 = g_map0t + (size_t)b * (H0c*W0c*DIM);
    const __half* m1 = g_map1t + (size_t)b * (H1c*W1c*DIM);

    float acc[8] = {0.f,0.f,0.f,0.f,0.f,0.f,0.f,0.f};

    #pragma unroll
    for (int p = 0; p < 16; p++) {
        float4 par = __ldg(&pp[p]);
        const __half* mp = (p < 8) ? m0 : m1;
        const int Wl = (p < 8) ? W0c : W1c;
        const int Hl = (p < 8) ? H0c : H1c;

        float x = par.x, y = par.y, wt = par.z;
        int x0 = (int)x, y0 = (int)y;
        float wx = x - (float)x0;
        float wy = y - (float)y0;
        int x1 = min(x0 + 1, Wl - 1);
        int y1 = min(y0 + 1, Hl - 1);

        uint4 u00 = __ldg((const uint4*)(mp + (size_t)(y0*Wl + x0) * DIM) + t);
        uint4 u01 = __ldg((const uint4*)(mp + (size_t)(y0*Wl + x1) * DIM) + t);
        uint4 u10 = __ldg((const uint4*)(mp + (size_t)(y1*Wl + x0) * DIM) + t);
        uint4 u11 = __ldg((const uint4*)(mp + (size_t)(y1*Wl + x1) * DIM) + t);

        float w00 = (1.f - wx) * (1.f - wy) * wt;
        float w01 = wx * (1.f - wy) * wt;
        float w10 = (1.f - wx) * wy * wt;
        float w11 = wx * wy * wt;

        const __half2* h00 = (const __half2*)&u00;
        const __half2* h01 = (const __half2*)&u01;
        const __half2* h10 = (const __half2*)&u10;
        const __half2* h11 = (const __half2*)&u11;
        #pragma unroll
        for (int i = 0; i < 4; i++) {
            float2 f00 = __half22float2(h00[i]);
            float2 f01 = __half22float2(h01[i]);
            float2 f10 = __half22float2(h10[i]);
            float2 f11 = __half22float2(h11[i]);
            acc[2*i]   = fmaf(w00, f00.x, fmaf(w01, f01.x, fmaf(w10, f10.x, fmaf(w11, f11.x, acc[2*i]))));
            acc[2*i+1] = fmaf(w00, f00.y, fmaf(w01, f01.y, fmaf(w10, f10.y, fmaf(w11, f11.y, acc[2*i+1]))));
        }
    }

    float4* dst = (float4*)(g_inner + (size_t)qi * DIM) + t*2;
    dst[0] = make_float4(acc[0], acc[1], acc[2], acc[3]);
    dst[1] = make_float4(acc[4], acc[5], acc[6], acc[7]);
}

// ---------------- 4) SGEMM double-buffered: out = g_inner @ Wout + bout -----
// M=32768, N=256, K=256. BM=BN=128, BK=8, 8x8 per thread, 256 threads.
__global__ void __launch_bounds__(256) gemm_kernel(const float* __restrict__ Wout,
                                                   const float* __restrict__ bout,
                                                   float* __restrict__ out)
{
    const int BM = 128, BN = 128, BK = 8;
    __shared__ __align__(16) float As[2][BK][BM];
    __shared__ __align__(16) float Bs[2][BK][BN];

    int bx = blockIdx.x;   // 0..1
    int by = blockIdx.y;   // 0..255
    int tid = threadIdx.x; // 256
    int tx = tid & 15;     // col group
    int ty = tid >> 4;     // row group

    const float* A  = g_inner + (size_t)by * BM * 256;
    const float* Bp = Wout + bx * BN;
    float* C = out + (size_t)by * BM * 256 + bx * BN;

    int arow = tid >> 1,  acol = (tid & 1) * 4;   // A tile load: 128x8
    int brow = tid >> 5,  bcol = (tid & 31) * 4;  // B tile load: 8x128

    float acc[8][8];
    #pragma unroll
    for (int i = 0; i < 8; i++)
        #pragma unroll
        for (int j = 0; j < 8; j++) acc[i][j] = 0.f;

    // prologue: load tile 0
    {
        float4 a4 = *(const float4*)(A + (size_t)arow * 256 + acol);
        As[0][acol + 0][arow] = a4.x;
        As[0][acol + 1][arow] = a4.y;
        As[0][acol + 2][arow] = a4.z;
        As[0][acol + 3][arow] = a4.w;
        float4 b4 = *(const float4*)(Bp + (size_t)brow * 256 + bcol);
        *(float4*)&Bs[0][brow][bcol] = b4;
    }
    __syncthreads();

    #pragma unroll 1
    for (int kt = 0; kt < 32; kt++) {
        int cur = kt & 1;
        float4 an, bn;
        if (kt < 31) {
            an = *(const float4*)(A + (size_t)arow * 256 + (kt+1)*BK + acol);
            bn = *(const float4*)(Bp + (size_t)((kt+1)*BK + brow) * 256 + bcol);
        }

        #pragma unroll
        for (int k = 0; k < BK; k++) {
            float4 ra0 = *(const float4*)&As[cur][k][ty*8];
            float4 ra1 = *(const float4*)&As[cur][k][ty*8 + 4];
            float4 rb0 = *(const float4*)&Bs[cur][k][tx*8];
            float4 rb1 = *(const float4*)&Bs[cur][k][tx*8 + 4];
            float ra[8] = {ra0.x, ra0.y, ra0.z, ra0.w, ra1.x, ra1.y, ra1.z, ra1.w};
            float rb[8] = {rb0.x, rb0.y, rb0.z, rb0.w, rb1.x, rb1.y, rb1.z, rb1.w};
            #pragma unroll
            for (int i = 0; i < 8; i++)
                #pragma unroll
                for (int j = 0; j < 8; j++)
                    acc[i][j] = fmaf(ra[i], rb[j], acc[i][j]);
        }

        if (kt < 31) {
            int nxt = cur ^ 1;
            As[nxt][acol + 0][arow] = an.x;
            As[nxt][acol + 1][arow] = an.y;
            As[nxt][acol + 2][arow] = an.z;
            As[nxt][acol + 3][arow] = an.w;
            *(float4*)&Bs[nxt][brow][bcol] = bn;
        }
        __syncthreads();
    }

    #pragma unroll
    for (int i = 0; i < 8; i++) {
        #pragma unroll
        for (int j = 0; j < 8; j += 4) {
            int col = bx * BN + tx * 8 + j;
            float4 r;
            r.x = acc[i][j + 0] + __ldg(&bout[col + 0]);
            r.y = acc[i][j + 1] + __ldg(&bout[col + 1]);
            r.z = acc[i][j + 2] + __ldg(&bout[col + 2]);
            r.w = acc[i][j + 3] + __ldg(&bout[col + 3]);
            *(float4*)(C + (size_t)(ty * 8 + i) * 256 + tx * 8 + j) = r;
        }
    }
}

// ---------------- launch -----------------------------------------------------
extern "C" void kernel_launch(void* const* d_in, const int* in_sizes, int n_in,
                              void* d_out, int out_size)
{
    const float* q        = (const float*)d_in[0];
    const float* map0     = (const float*)d_in[1];
    const float* map1     = (const float*)d_in[2];
    const float* base_ref = (const float*)d_in[3];
    const float* Wrd      = (const float*)d_in[4];
    const float* brd      = (const float*)d_in[5];
    const float* Woff     = (const float*)d_in[6];
    const float* boff     = (const float*)d_in[7];
    const float* Wattn    = (const float*)d_in[8];
    const float* battn    = (const float*)d_in[9];
    const float* Wout     = (const float*)d_in[10];
    const float* bout     = (const float*)d_in[11];
    float* out = (float*)d_out;

    wprep_kernel<<<NOUT, 256>>>(Wrd, brd, Woff, boff, Wattn, battn);

    transpose_kernel<<<dim3(W0c/32, DIM/32, BATCH*H0c), dim3(32, 8)>>>(map0, H0c, W0c, 0);
    transpose_kernel<<<dim3(W1c/32, DIM/32, BATCH*H1c), dim3(32, 8)>>>(map1, H1c, W1c, 1);

    proj_gemm_kernel<<<NQ/PBM, 256>>>(q, base_ref);

    sample_kernel<<<NQ/16, 512>>>();

    gemm_kernel<<<dim3(2, NQ/128), 256>>>(Wout, bout, out);
}

// round 6
// speedup vs baseline: 2.2928x; 1.3224x over previous
#include <cuda_runtime.h>
#include <cuda_fp16.h>
#include <mma.h>
#include <math.h>

using namespace nvcuda;

#define BATCH 4
#define QN    8192
#define DIM   256
#define NQ    (BATCH*QN)        // 32768
#define H0c   128
#define W0c   128
#define H1c   64
#define W1c   64
#define LPTS  16                // L*P
#define NOUT  52                // 4 rd + 32 off + 16 attn
#define NPAD  64                // padded N for proj GEMM
#define EPSV  1e-5f

typedef unsigned long long ull;

// packed f32x2 FMA: acc = a*b + acc (elementwise on 2 packed fp32)
__device__ __forceinline__ void ffma2(ull& acc, ull a, ull b) {
    asm("fma.rn.f32x2 %0, %1, %2, %0;" : "+l"(acc) : "l"(a), "l"(b));
}
__device__ __forceinline__ float2 u2f(ull u) {
    float2 f;
    asm("mov.b64 {%0,%1}, %2;" : "=f"(f.x), "=f"(f.y) : "l"(u));
    return f;
}

// ---------------- scratch (static device arrays; no allocation allowed) ----
__device__ __half g_map0t[BATCH*H0c*W0c*DIM];   // (B,H,W,D) fp16
__device__ __half g_map1t[BATCH*H1c*W1c*DIM];   // (B,H,W,D) fp16
__device__ __half g_innerh[(size_t)NQ*DIM];     // fp16 inner
__device__ __half g_Wouth[DIM*DIM];             // fp16 Wout
__device__ float  g_biasmat[16*DIM];            // 16 replicated bias rows
__device__ float4 g_params[(size_t)NQ*LPTS];    // x, y, attn_w, pad
__device__ float  g_Wk[DIM*NPAD];               // k-major fused weights (cols 52..63 stay 0)
__device__ float  g_bias[NOUT];

// ---------------- 0a) weight prep: fuse into k-major layout -----------------
__global__ void wprep_kernel(const float* __restrict__ Wrd,   const float* __restrict__ brd,
                             const float* __restrict__ Woff,  const float* __restrict__ boff,
                             const float* __restrict__ Wattn, const float* __restrict__ battn)
{
    int j = blockIdx.x;          // 0..51
    int d = threadIdx.x;         // 0..255
    float v;
    if (j < 4)        v = Wrd [d*4  + j];
    else if (j < 36)  v = Woff[d*32 + (j-4)];
    else              v = Wattn[d*16 + (j-36)];
    g_Wk[d*NPAD + j] = v;
    if (d == 0) {
        float bv;
        if (j < 4)        bv = brd[j];
        else if (j < 36)  bv = boff[j-4];
        else              bv = battn[j-36];
        g_bias[j] = bv;
    }
}

// ---------------- 0b) Wout -> fp16, bias -> replicated rows -----------------
__global__ void wconv_kernel(const float* __restrict__ Wout, const float* __restrict__ bout)
{
    int idx = blockIdx.x * 256 + threadIdx.x;    // grid 256 -> 65536 = DIM*DIM
    g_Wouth[idx] = __float2half(Wout[idx]);
    if (idx < 16*DIM) g_biasmat[idx] = bout[idx & (DIM-1)];
}

// ---------------- 1) transpose (B,D,H,W) fp32 -> (B,H,W,D) fp16 -------------
__global__ void transpose_kernel(const float* __restrict__ src, int H, int W, int which)
{
    __half* dst = which ? g_map1t : g_map0t;
    __shared__ float tile[32][33];
    int w0 = blockIdx.x * 32;
    int d0 = blockIdx.y * 32;
    int bh = blockIdx.z;
    int b  = bh / H;
    int h  = bh % H;
    int tx = threadIdx.x, ty = threadIdx.y;   // 32 x 8

    const float* s = src + (((size_t)b*DIM + d0)*H + h) * W + w0;
    #pragma unroll
    for (int r = 0; r < 4; r++)
        tile[ty + 8*r][tx] = s[(size_t)(ty + 8*r) * H * W + tx];
    __syncthreads();
    __half* dbase = dst + (((size_t)b*H + h)*W + w0) * DIM + d0;
    #pragma unroll
    for (int r = 0; r < 4; r++)
        dbase[(size_t)(ty + 8*r) * DIM + tx] = __float2half(tile[tx][ty + 8*r]);
}

// ---------------- 2) fused projection GEMM + point-param prep ---------------
// (PBM=128 version — known-good 45.4us; PBM=64 regressed to LDS-bound)
#define PBM 128
#define PBK 32
#define STAGE_PITCH 132
#define PROJ_SMEM (NPAD*STAGE_PITCH*4)   // 33792 B (>= As 16K + Bsd 16K)

__global__ void __launch_bounds__(256) proj_gemm_kernel(const float* __restrict__ q,
                                                        const float* __restrict__ base_ref)
{
    __shared__ __align__(16) char sm[PROJ_SMEM];
    float  (*As)[PBM]  = (float  (*)[PBM]) sm;                  // [PBK][PBM]
    float2 (*Bsd)[NPAD]= (float2 (*)[NPAD])(sm + PBK*PBM*4);    // [PBK][NPAD] dup pairs
    float* stage = (float*)sm;                                   // [NPAD][STAGE_PITCH]

    int tid = threadIdx.x;
    int q0  = blockIdx.x * PBM;
    int tm  = tid & 31;          // query group: queries tm*4 .. tm*4+3
    int tn  = tid >> 5;          // output group: outputs tn*8 .. tn*8+7

    ull acc[2][8];
    #pragma unroll
    for (int p = 0; p < 2; p++)
        #pragma unroll
        for (int j = 0; j < 8; j++) acc[p][j] = 0ull;

    #pragma unroll 1
    for (int kt = 0; kt < DIM/PBK; kt++) {
        int k0 = kt * PBK;
        // load A tile (transposed into [k][m])
        {
            int r = tid >> 1, cb = (tid & 1) * 16;
            #pragma unroll
            for (int i = 0; i < 4; i++) {
                float4 v = *(const float4*)(q + (size_t)(q0 + r)*DIM + k0 + cb + i*4);
                As[cb + i*4 + 0][r] = v.x;
                As[cb + i*4 + 1][r] = v.y;
                As[cb + i*4 + 2][r] = v.z;
                As[cb + i*4 + 3][r] = v.w;
            }
        }
        // load B tile duplicated: Bsd[k][j] = (w, w)
        {
            int kr = tid >> 3, jb = (tid & 7) * 8;
            #pragma unroll
            for (int i = 0; i < 2; i++) {
                float4 w = *(const float4*)(g_Wk + (size_t)(k0 + kr)*NPAD + jb + i*4);
                Bsd[kr][jb + i*4 + 0] = make_float2(w.x, w.x);
                Bsd[kr][jb + i*4 + 1] = make_float2(w.y, w.y);
                Bsd[kr][jb + i*4 + 2] = make_float2(w.z, w.z);
                Bsd[kr][jb + i*4 + 3] = make_float2(w.w, w.w);
            }
        }
        __syncthreads();

        #pragma unroll
        for (int k = 0; k < PBK; k++) {
            longlong2 av = *(const longlong2*)&As[k][tm*4];   // (q0,q1),(q2,q3)
            ull bq[8];
            #pragma unroll
            for (int i = 0; i < 4; i++) {
                longlong2 bv = *((const longlong2*)&Bsd[k][tn*8] + i);
                bq[2*i]   = (ull)bv.x;
                bq[2*i+1] = (ull)bv.y;
            }
            #pragma unroll
            for (int j = 0; j < 8; j++) {
                ffma2(acc[0][j], (ull)av.x, bq[j]);
                ffma2(acc[1][j], (ull)av.y, bq[j]);
            }
        }
        __syncthreads();
    }

    // stage acc -> smem as stage[j][query]
    #pragma unroll
    for (int j = 0; j < 8; j++) {
        #pragma unroll
        for (int p = 0; p < 2; p++) {
            float2 v = u2f(acc[p][j]);
            *(float2*)&stage[(tn*8 + j)*STAGE_PITCH + tm*4 + p*2] = v;
        }
    }
    __syncthreads();

    // epilogue: one thread per query does softmax + coords
    if (tid < PBM) {
        int qi = q0 + tid;
        int b  = qi >> 13;

        float r[NOUT];
        #pragma unroll
        for (int j = 0; j < NOUT; j++)
            r[j] = stage[j*STAGE_PITCH + tid] + g_bias[j];

        // softmax over r[36..51]
        float m = -1e30f;
        #pragma unroll
        for (int j = 0; j < 16; j++) m = fmaxf(m, r[36+j]);
        float sum = 0.f;
        float e[16];
        #pragma unroll
        for (int j = 0; j < 16; j++) { e[j] = expf(r[36+j] - m); sum += e[j]; }
        float inv = 1.f / sum;

        float4* pp = g_params + (size_t)qi * LPTS;
        #pragma unroll
        for (int l = 0; l < 2; l++) {
            float Wf = l ? (float)W1c : (float)W0c;
            float Hf = l ? (float)H1c : (float)H0c;
            float bx = base_ref[b*4 + l*2 + 0];
            float by = base_ref[b*4 + l*2 + 1];
            bx = fminf(fmaxf(bx, EPSV), 1.f - EPSV);
            by = fminf(fmaxf(by, EPSV), 1.f - EPSV);
            float lbx = logf(bx / (1.f - bx));
            float lby = logf(by / (1.f - by));
            float refx = 1.f / (1.f + expf(-(lbx + r[l*2 + 0])));
            float refy = 1.f / (1.f + expf(-(lby + r[l*2 + 1])));

            #pragma unroll
            for (int p = 0; p < 8; p++) {
                int pt = l*8 + p;
                float ox = r[4 + pt*2 + 0];
                float oy = r[4 + pt*2 + 1];
                float lx = refx + ox / Wf;
                float ly = refy + oy / Hf;
                if (l == 1) ly = ly - floorf(ly);      // jnp.remainder(., 1.0)
                float x = lx * Wf - 0.5f;
                float y = ly * Hf - 0.5f;
                x = fminf(fmaxf(x, 0.f), Wf - 1.f);
                y = fminf(fmaxf(y, 0.f), Hf - 1.f);
                pp[pt] = make_float4(x, y, e[pt]*inv, 0.f);
            }
        }
    }
}

// ---------------- 3) sampling: fp16 maps, 1 warp per query, fp16 inner ------
__global__ void __launch_bounds__(512) sample_kernel()
{
    int g  = threadIdx.x >> 5;           // 16 queries per 512-thread block
    int t  = threadIdx.x & 31;           // channel group: channels 8t..8t+7
    int qi = blockIdx.x * 16 + g;
    int b  = qi >> 13;

    const float4* pp = g_params + (size_t)qi * LPTS;
    const __half* m0 = g_map0t + (size_t)b * (H0c*W0c*DIM);
    const __half* m1 = g_map1t + (size_t)b * (H1c*W1c*DIM);

    float acc[8] = {0.f,0.f,0.f,0.f,0.f,0.f,0.f,0.f};

    #pragma unroll
    for (int p = 0; p < 16; p++) {
        float4 par = __ldg(&pp[p]);
        const __half* mp = (p < 8) ? m0 : m1;
        const int Wl = (p < 8) ? W0c : W1c;
        const int Hl = (p < 8) ? H0c : H1c;

        float x = par.x, y = par.y, wt = par.z;
        int x0 = (int)x, y0 = (int)y;
        float wx = x - (float)x0;
        float wy = y - (float)y0;
        int x1 = min(x0 + 1, Wl - 1);
        int y1 = min(y0 + 1, Hl - 1);

        uint4 u00 = __ldg((const uint4*)(mp + (size_t)(y0*Wl + x0) * DIM) + t);
        uint4 u01 = __ldg((const uint4*)(mp + (size_t)(y0*Wl + x1) * DIM) + t);
        uint4 u10 = __ldg((const uint4*)(mp + (size_t)(y1*Wl + x0) * DIM) + t);
        uint4 u11 = __ldg((const uint4*)(mp + (size_t)(y1*Wl + x1) * DIM) + t);

        float w00 = (1.f - wx) * (1.f - wy) * wt;
        float w01 = wx * (1.f - wy) * wt;
        float w10 = (1.f - wx) * wy * wt;
        float w11 = wx * wy * wt;

        const __half2* h00 = (const __half2*)&u00;
        const __half2* h01 = (const __half2*)&u01;
        const __half2* h10 = (const __half2*)&u10;
        const __half2* h11 = (const __half2*)&u11;
        #pragma unroll
        for (int i = 0; i < 4; i++) {
            float2 f00 = __half22float2(h00[i]);
            float2 f01 = __half22float2(h01[i]);
            float2 f10 = __half22float2(h10[i]);
            float2 f11 = __half22float2(h11[i]);
            acc[2*i]   = fmaf(w00, f00.x, fmaf(w01, f01.x, fmaf(w10, f10.x, fmaf(w11, f11.x, acc[2*i]))));
            acc[2*i+1] = fmaf(w00, f00.y, fmaf(w01, f01.y, fmaf(w10, f10.y, fmaf(w11, f11.y, acc[2*i+1]))));
        }
    }

    __half2 ph[4];
    #pragma unroll
    for (int i = 0; i < 4; i++)
        ph[i] = __floats2half2_rn(acc[2*i], acc[2*i+1]);
    *(uint4*)(g_innerh + (size_t)qi * DIM + t*8) = *(uint4*)ph;
}

// ---------------- 4) WMMA GEMM: out = g_innerh @ g_Wouth + bias -------------
// M=32768, N=256, K=256. Block = 4 warps; block tile 64x128; warp tile 64x32.
// Fragments loaded directly from global (all operands L2-resident).
__global__ void __launch_bounds__(128) gemm_wmma_kernel(float* __restrict__ out)
{
    int warp = threadIdx.x >> 5;                 // 0..3
    int m0 = blockIdx.x * 64;
    int n0 = blockIdx.y * 128 + warp * 32;

    wmma::fragment<wmma::accumulator, 16, 16, 16, float> acc[4][2];
    #pragma unroll
    for (int i = 0; i < 4; i++)
        #pragma unroll
        for (int j = 0; j < 2; j++)
            wmma::load_matrix_sync(acc[i][j], g_biasmat + n0 + 16*j, DIM, wmma::mem_row_major);

    #pragma unroll 1
    for (int k = 0; k < DIM; k += 16) {
        wmma::fragment<wmma::matrix_a, 16, 16, 16, __half, wmma::row_major> a[4];
        wmma::fragment<wmma::matrix_b, 16, 16, 16, __half, wmma::row_major> bfr[2];
        #pragma unroll
        for (int i = 0; i < 4; i++)
            wmma::load_matrix_sync(a[i], g_innerh + (size_t)(m0 + 16*i)*DIM + k, DIM);
        #pragma unroll
        for (int j = 0; j < 2; j++)
            wmma::load_matrix_sync(bfr[j], g_Wouth + (size_t)k*DIM + n0 + 16*j, DIM);
        #pragma unroll
        for (int i = 0; i < 4; i++)
            #pragma unroll
            for (int j = 0; j < 2; j++)
                wmma::mma_sync(acc[i][j], a[i], bfr[j], acc[i][j]);
    }

    #pragma unroll
    for (int i = 0; i < 4; i++)
        #pragma unroll
        for (int j = 0; j < 2; j++)
            wmma::store_matrix_sync(out + (size_t)(m0 + 16*i)*DIM + n0 + 16*j,
                                    acc[i][j], DIM, wmma::mem_row_major);
}

// ---------------- launch -----------------------------------------------------
extern "C" void kernel_launch(void* const* d_in, const int* in_sizes, int n_in,
                              void* d_out, int out_size)
{
    const float* q        = (const float*)d_in[0];
    const float* map0     = (const float*)d_in[1];
    const float* map1     = (const float*)d_in[2];
    const float* base_ref = (const float*)d_in[3];
    const float* Wrd      = (const float*)d_in[4];
    const float* brd      = (const float*)d_in[5];
    const float* Woff     = (const float*)d_in[6];
    const float* boff     = (const float*)d_in[7];
    const float* Wattn    = (const float*)d_in[8];
    const float* battn    = (const float*)d_in[9];
    const float* Wout     = (const float*)d_in[10];
    const float* bout     = (const float*)d_in[11];
    float* out = (float*)d_out;

    wprep_kernel<<<NOUT, 256>>>(Wrd, brd, Woff, boff, Wattn, battn);
    wconv_kernel<<<DIM*DIM/256, 256>>>(Wout, bout);

    transpose_kernel<<<dim3(W0c/32, DIM/32, BATCH*H0c), dim3(32, 8)>>>(map0, H0c, W0c, 0);
    transpose_kernel<<<dim3(W1c/32, DIM/32, BATCH*H1c), dim3(32, 8)>>>(map1, H1c, W1c, 1);

    proj_gemm_kernel<<<NQ/PBM, 256>>>(q, base_ref);

    sample_kernel<<<NQ/16, 512>>>();

    gemm_wmma_kernel<<<dim3(NQ/64, DIM/128), 128>>>(out);
}

// round 7
// speedup vs baseline: 2.6473x; 1.1546x over previous
#include <cuda_runtime.h>
#include <cuda_fp16.h>
#include <mma.h>
#include <math.h>

using namespace nvcuda;

#define BATCH 4
#define QN    8192
#define DIM   256
#define NQ    (BATCH*QN)        // 32768
#define H0c   128
#define W0c   128
#define H1c   64
#define W1c   64
#define LPTS  16                // L*P
#define NOA   48                // 32 off + 16 attn (tf32 path)
#define EPSV  1e-5f

// ---------------- scratch (static device arrays; no allocation allowed) ----
__device__ __half g_map0t[BATCH*H0c*W0c*DIM];   // (B,H,W,D) fp16
__device__ __half g_map1t[BATCH*H1c*W1c*DIM];   // (B,H,W,D) fp16
__device__ __half g_innerh[(size_t)NQ*DIM];     // fp16 inner
__device__ __half g_Wouth[DIM*DIM];             // fp16 Wout
__device__ float  g_biasmat[16*DIM];            // 16 replicated bias rows
__device__ float4 g_params[(size_t)NQ*LPTS];    // x, y, attn_w, pad
__device__ float  g_rd[(size_t)NQ*4];           // fp32 ref-delta (incl. brd)
__device__ float  g_oa[(size_t)NQ*NOA];         // fp32 offsets+attn logits (raw)

// ---------------- 0) Wout -> fp16, bias -> replicated rows ------------------
__global__ void wconv_kernel(const float* __restrict__ Wout, const float* __restrict__ bout)
{
    int idx = blockIdx.x * 256 + threadIdx.x;    // 65536 = DIM*DIM
    g_Wouth[idx] = __float2half(Wout[idx]);
    if (idx < 16*DIM) g_biasmat[idx] = bout[idx & (DIM-1)];
}

// ---------------- 1) transpose (B,D,H,W) fp32 -> (B,H,W,D) fp16 -------------
__global__ void transpose_kernel(const float* __restrict__ src, int H, int W, int which)
{
    __half* dst = which ? g_map1t : g_map0t;
    __shared__ float tile[32][33];
    int w0 = blockIdx.x * 32;
    int d0 = blockIdx.y * 32;
    int bh = blockIdx.z;
    int b  = bh / H;
    int h  = bh % H;
    int tx = threadIdx.x, ty = threadIdx.y;   // 32 x 8

    const float* s = src + (((size_t)b*DIM + d0)*H + h) * W + w0;
    #pragma unroll
    for (int r = 0; r < 4; r++)
        tile[ty + 8*r][tx] = s[(size_t)(ty + 8*r) * H * W + tx];
    __syncthreads();
    __half* dbase = dst + (((size_t)b*H + h)*W + w0) * DIM + d0;
    #pragma unroll
    for (int r = 0; r < 4; r++)
        dbase[(size_t)(ty + 8*r) * DIM + tx] = __float2half(tile[tx][ty + 8*r]);
}

// ---------------- 2a) fp32 ref-delta: warp per query (precision-critical) ---
__global__ void proj_rd_kernel(const float* __restrict__ q,
                               const float* __restrict__ Wrd,
                               const float* __restrict__ brd)
{
    int warp = (blockIdx.x * blockDim.x + threadIdx.x) >> 5;
    int lane = threadIdx.x & 31;
    if (warp >= NQ) return;

    const float* qr = q + (size_t)warp * DIM;
    float qv[8];
    #pragma unroll
    for (int i = 0; i < 8; i++) qv[i] = qr[lane + 32*i];

    float s[4];
    #pragma unroll
    for (int j = 0; j < 4; j++) {
        float t = 0.f;
        #pragma unroll
        for (int i = 0; i < 8; i++) t = fmaf(qv[i], __ldg(&Wrd[(lane + 32*i)*4 + j]), t);
        #pragma unroll
        for (int o = 16; o; o >>= 1) t += __shfl_xor_sync(0xffffffffu, t, o);
        s[j] = t;
    }
    if (lane == 0) {
        float4 r;
        r.x = s[0] + __ldg(&brd[0]);
        r.y = s[1] + __ldg(&brd[1]);
        r.z = s[2] + __ldg(&brd[2]);
        r.w = s[3] + __ldg(&brd[3]);
        *(float4*)&g_rd[(size_t)warp*4] = r;
    }
}

// ---------------- 2b) tf32 WMMA: q @ [Woff|Wattn] -> g_oa (48 cols) ---------
// Block: 128 queries, 4 warps (each warp 32q x 48out). B (256x48) resident in smem.
#define OA_SMEM (256*48*4 + 128*8*4)   // 49152 + 4096 = 53248
__global__ void __launch_bounds__(128) proj_oa_kernel(const float* __restrict__ q,
                                                      const float* __restrict__ Woff,
                                                      const float* __restrict__ Wattn)
{
    extern __shared__ char sm_oa[];
    float (*Bs)[NOA] = (float (*)[NOA])sm_oa;           // [256][48]
    float (*As)[8]   = (float (*)[8])(sm_oa + 256*NOA*4); // [128][8]

    int tid  = threadIdx.x;
    int warp = tid >> 5;
    int q0   = blockIdx.x * 128;

    // load B once: Woff [256][32] + Wattn [256][16]
    #pragma unroll
    for (int i = 0; i < 16; i++) {           // 2048 float4 of Woff
        int f4 = i*128 + tid;
        int row = f4 >> 3, c4 = f4 & 7;
        *(float4*)&Bs[row][c4*4] = __ldg((const float4*)(Woff + (size_t)row*32 + c4*4));
    }
    #pragma unroll
    for (int i = 0; i < 8; i++) {            // 1024 float4 of Wattn
        int f4 = i*128 + tid;
        int row = f4 >> 2, c4 = f4 & 3;
        *(float4*)&Bs[row][32 + c4*4] = __ldg((const float4*)(Wattn + (size_t)row*16 + c4*4));
    }

    wmma::fragment<wmma::accumulator, 16, 16, 8, float> acc[2][3];
    #pragma unroll
    for (int i = 0; i < 2; i++)
        #pragma unroll
        for (int j = 0; j < 3; j++)
            wmma::fill_fragment(acc[i][j], 0.f);

    #pragma unroll 1
    for (int kt = 0; kt < 32; kt++) {
        __syncthreads();
        // stage A: 128 rows x 8 k-cols
        *(float4*)&As[tid][0] = *(const float4*)(q + (size_t)(q0 + tid)*DIM + kt*8);
        *(float4*)&As[tid][4] = *(const float4*)(q + (size_t)(q0 + tid)*DIM + kt*8 + 4);
        __syncthreads();

        wmma::fragment<wmma::matrix_a, 16, 16, 8, wmma::precision::tf32, wmma::row_major> a[2];
        wmma::fragment<wmma::matrix_b, 16, 16, 8, wmma::precision::tf32, wmma::row_major> bf[3];
        #pragma unroll
        for (int i = 0; i < 2; i++) {
            wmma::load_matrix_sync(a[i], &As[warp*32 + 16*i][0], 8);
            #pragma unroll
            for (int t = 0; t < a[i].num_elements; t++)
                a[i].x[t] = wmma::__float_to_tf32(a[i].x[t]);
        }
        #pragma unroll
        for (int j = 0; j < 3; j++) {
            wmma::load_matrix_sync(bf[j], &Bs[kt*8][16*j], NOA);
            #pragma unroll
            for (int t = 0; t < bf[j].num_elements; t++)
                bf[j].x[t] = wmma::__float_to_tf32(bf[j].x[t]);
        }
        #pragma unroll
        for (int i = 0; i < 2; i++)
            #pragma unroll
            for (int j = 0; j < 3; j++)
                wmma::mma_sync(acc[i][j], a[i], bf[j], acc[i][j]);
    }

    #pragma unroll
    for (int i = 0; i < 2; i++)
        #pragma unroll
        for (int j = 0; j < 3; j++)
            wmma::store_matrix_sync(g_oa + (size_t)(q0 + warp*32 + 16*i)*NOA + 16*j,
                                    acc[i][j], NOA, wmma::mem_row_major);
}

// ---------------- 2c) prep: softmax/sigmoid/coords -> g_params --------------
__global__ void __launch_bounds__(128) prep_kernel(const float* __restrict__ base_ref,
                                                   const float* __restrict__ boff,
                                                   const float* __restrict__ battn)
{
    __shared__ float soa[128][NOA];     // 24KB
    int tid = threadIdx.x;
    int q0  = blockIdx.x * 128;

    #pragma unroll
    for (int i = 0; i < 12; i++) {      // 1536 float4
        int f4 = i*128 + tid;
        int qq = f4 / 12, c4 = f4 % 12;
        *(float4*)&soa[qq][c4*4] = *(const float4*)(g_oa + (size_t)(q0 + qq)*NOA + c4*4);
    }
    __syncthreads();

    int qi = q0 + tid;
    int b  = qi >> 13;

    float4 rdv = *(const float4*)&g_rd[(size_t)qi*4];
    float rd[4] = {rdv.x, rdv.y, rdv.z, rdv.w};

    float lg[16];
    float m = -1e30f;
    #pragma unroll
    for (int j = 0; j < 16; j++) {
        lg[j] = soa[tid][32 + j] + __ldg(&battn[j]);
        m = fmaxf(m, lg[j]);
    }
    float sum = 0.f;
    #pragma unroll
    for (int j = 0; j < 16; j++) { lg[j] = expf(lg[j] - m); sum += lg[j]; }
    float inv = 1.f / sum;

    float4* pp = g_params + (size_t)qi * LPTS;
    #pragma unroll
    for (int l = 0; l < 2; l++) {
        float Wf = l ? (float)W1c : (float)W0c;
        float Hf = l ? (float)H1c : (float)H0c;
        float bx = base_ref[b*4 + l*2 + 0];
        float by = base_ref[b*4 + l*2 + 1];
        bx = fminf(fmaxf(bx, EPSV), 1.f - EPSV);
        by = fminf(fmaxf(by, EPSV), 1.f - EPSV);
        float lbx = logf(bx / (1.f - bx));
        float lby = logf(by / (1.f - by));
        float refx = 1.f / (1.f + expf(-(lbx + rd[l*2 + 0])));
        float refy = 1.f / (1.f + expf(-(lby + rd[l*2 + 1])));

        #pragma unroll
        for (int p = 0; p < 8; p++) {
            int pt = l*8 + p;
            float ox = soa[tid][pt*2 + 0] + __ldg(&boff[pt*2 + 0]);
            float oy = soa[tid][pt*2 + 1] + __ldg(&boff[pt*2 + 1]);
            float lx = refx + ox / Wf;
            float ly = refy + oy / Hf;
            if (l == 1) ly = ly - floorf(ly);      // jnp.remainder(., 1.0)
            float x = lx * Wf - 0.5f;
            float y = ly * Hf - 0.5f;
            x = fminf(fmaxf(x, 0.f), Wf - 1.f);
            y = fminf(fmaxf(y, 0.f), Hf - 1.f);
            pp[pt] = make_float4(x, y, lg[pt]*inv, 0.f);
        }
    }
}

// ---------------- 3) sampling: fp16 maps, 1 warp per query, fp16 inner ------
__global__ void __launch_bounds__(512) sample_kernel()
{
    int g  = threadIdx.x >> 5;           // 16 queries per 512-thread block
    int t  = threadIdx.x & 31;           // channel group: channels 8t..8t+7
    int qi = blockIdx.x * 16 + g;
    int b  = qi >> 13;

    const float4* pp = g_params + (size_t)qi * LPTS;
    const __half* m0 = g_map0t + (size_t)b * (H0c*W0c*DIM);
    const __half* m1 = g_map1t + (size_t)b * (H1c*W1c*DIM);

    float acc[8] = {0.f,0.f,0.f,0.f,0.f,0.f,0.f,0.f};

    #pragma unroll
    for (int p = 0; p < 16; p++) {
        float4 par = __ldg(&pp[p]);
        const __half* mp = (p < 8) ? m0 : m1;
        const int Wl = (p < 8) ? W0c : W1c;
        const int Hl = (p < 8) ? H0c : H1c;

        float x = par.x, y = par.y, wt = par.z;
        int x0 = (int)x, y0 = (int)y;
        float wx = x - (float)x0;
        float wy = y - (float)y0;
        int x1 = min(x0 + 1, Wl - 1);
        int y1 = min(y0 + 1, Hl - 1);

        uint4 u00 = __ldg((const uint4*)(mp + (size_t)(y0*Wl + x0) * DIM) + t);
        uint4 u01 = __ldg((const uint4*)(mp + (size_t)(y0*Wl + x1) * DIM) + t);
        uint4 u10 = __ldg((const uint4*)(mp + (size_t)(y1*Wl + x0) * DIM) + t);
        uint4 u11 = __ldg((const uint4*)(mp + (size_t)(y1*Wl + x1) * DIM) + t);

        float w00 = (1.f - wx) * (1.f - wy) * wt;
        float w01 = wx * (1.f - wy) * wt;
        float w10 = (1.f - wx) * wy * wt;
        float w11 = wx * wy * wt;

        const __half2* h00 = (const __half2*)&u00;
        const __half2* h01 = (const __half2*)&u01;
        const __half2* h10 = (const __half2*)&u10;
        const __half2* h11 = (const __half2*)&u11;
        #pragma unroll
        for (int i = 0; i < 4; i++) {
            float2 f00 = __half22float2(h00[i]);
            float2 f01 = __half22float2(h01[i]);
            float2 f10 = __half22float2(h10[i]);
            float2 f11 = __half22float2(h11[i]);
            acc[2*i]   = fmaf(w00, f00.x, fmaf(w01, f01.x, fmaf(w10, f10.x, fmaf(w11, f11.x, acc[2*i]))));
            acc[2*i+1] = fmaf(w00, f00.y, fmaf(w01, f01.y, fmaf(w10, f10.y, fmaf(w11, f11.y, acc[2*i+1]))));
        }
    }

    __half2 ph[4];
    #pragma unroll
    for (int i = 0; i < 4; i++)
        ph[i] = __floats2half2_rn(acc[2*i], acc[2*i+1]);
    *(uint4*)(g_innerh + (size_t)qi * DIM + t*8) = *(uint4*)ph;
}

// ---------------- 4) WMMA GEMM (smem-staged): out = inner @ Wout + bias -----
// Block tile 64x128, 4 warps (warp 64x32... warp owns n-slice of 32), K=256.
#define APITCH 264
#define BPITCH 136
#define GEMM_SMEM (64*APITCH*2 + 256*BPITCH*2)   // 33792 + 69632 = 103424
__global__ void __launch_bounds__(128) gemm_wmma_kernel(float* __restrict__ out)
{
    extern __shared__ char sm_g[];
    __half (*Ash)[APITCH] = (__half (*)[APITCH])sm_g;            // [64][264]
    __half (*Bsh)[BPITCH] = (__half (*)[BPITCH])(sm_g + 64*APITCH*2); // [256][136]

    int tid  = threadIdx.x;
    int warp = tid >> 5;
    int m0 = blockIdx.x * 64;
    int nb = blockIdx.y * 128;
    int n0 = nb + warp * 32;

    // stage A: 64 x 256 fp16 (2048 uint4)
    #pragma unroll
    for (int i = 0; i < 16; i++) {
        int f = i*128 + tid;
        int row = f >> 5, c8 = f & 31;
        *(uint4*)&Ash[row][c8*8] = *(const uint4*)(g_innerh + (size_t)(m0 + row)*DIM + c8*8);
    }
    // stage B: 256 x 128 fp16 (4096 uint4)
    #pragma unroll
    for (int i = 0; i < 32; i++) {
        int f = i*128 + tid;
        int row = f >> 4, c8 = f & 15;
        *(uint4*)&Bsh[row][c8*8] = *(const uint4*)(g_Wouth + (size_t)row*DIM + nb + c8*8);
    }

    wmma::fragment<wmma::accumulator, 16, 16, 16, float> acc[4][2];
    #pragma unroll
    for (int i = 0; i < 4; i++)
        #pragma unroll
        for (int j = 0; j < 2; j++)
            wmma::load_matrix_sync(acc[i][j], g_biasmat + n0 + 16*j, DIM, wmma::mem_row_major);

    __syncthreads();

    #pragma unroll 1
    for (int k = 0; k < DIM; k += 16) {
        wmma::fragment<wmma::matrix_a, 16, 16, 16, __half, wmma::row_major> a[4];
        wmma::fragment<wmma::matrix_b, 16, 16, 16, __half, wmma::row_major> bfr[2];
        #pragma unroll
        for (int i = 0; i < 4; i++)
            wmma::load_matrix_sync(a[i], &Ash[16*i][k], APITCH);
        #pragma unroll
        for (int j = 0; j < 2; j++)
            wmma::load_matrix_sync(bfr[j], &Bsh[k][warp*32 + 16*j], BPITCH);
        #pragma unroll
        for (int i = 0; i < 4; i++)
            #pragma unroll
            for (int j = 0; j < 2; j++)
                wmma::mma_sync(acc[i][j], a[i], bfr[j], acc[i][j]);
    }

    #pragma unroll
    for (int i = 0; i < 4; i++)
        #pragma unroll
        for (int j = 0; j < 2; j++)
            wmma::store_matrix_sync(out + (size_t)(m0 + 16*i)*DIM + n0 + 16*j,
                                    acc[i][j], DIM, wmma::mem_row_major);
}

// ---------------- launch -----------------------------------------------------
extern "C" void kernel_launch(void* const* d_in, const int* in_sizes, int n_in,
                              void* d_out, int out_size)
{
    const float* q        = (const float*)d_in[0];
    const float* map0     = (const float*)d_in[1];
    const float* map1     = (const float*)d_in[2];
    const float* base_ref = (const float*)d_in[3];
    const float* Wrd      = (const float*)d_in[4];
    const float* brd      = (const float*)d_in[5];
    const float* Woff     = (const float*)d_in[6];
    const float* boff     = (const float*)d_in[7];
    const float* Wattn    = (const float*)d_in[8];
    const float* battn    = (const float*)d_in[9];
    const float* Wout     = (const float*)d_in[10];
    const float* bout     = (const float*)d_in[11];
    float* out = (float*)d_out;

    static bool attrs_set = false;
    if (!attrs_set) {
        cudaFuncSetAttribute(proj_oa_kernel, cudaFuncAttributeMaxDynamicSharedMemorySize, OA_SMEM);
        cudaFuncSetAttribute(gemm_wmma_kernel, cudaFuncAttributeMaxDynamicSharedMemorySize, GEMM_SMEM);
        attrs_set = true;
    }

    wconv_kernel<<<DIM*DIM/256, 256>>>(Wout, bout);

    transpose_kernel<<<dim3(W0c/32, DIM/32, BATCH*H0c), dim3(32, 8)>>>(map0, H0c, W0c, 0);
    transpose_kernel<<<dim3(W1c/32, DIM/32, BATCH*H1c), dim3(32, 8)>>>(map1, H1c, W1c, 1);

    proj_rd_kernel<<<NQ/8, 256>>>(q, Wrd, brd);
    proj_oa_kernel<<<NQ/128, 128, OA_SMEM>>>(q, Woff, Wattn);
    prep_kernel<<<NQ/128, 128>>>(base_ref, boff, battn);

    sample_kernel<<<NQ/16, 512>>>();

    gemm_wmma_kernel<<<dim3(NQ/64, 2), 128, GEMM_SMEM>>>(out);
}